// round 9
// baseline (speedup 1.0000x reference)
#include <cuda_runtime.h>
#include <cuda_fp16.h>
#include <cstdint>

#define NPOS 48             // positions per block; 4032 = 84*48
#define TPB  84
#define NTILES 6            // NPOS/8
#define SM_STAGE 24576      // act buffer is [0, 24576)
#define SMEM_TOTAL (24576 + 8 * 4096)   // + 8 warps x 2 bufs x 2KB W staging = 57344

// Fragment-major FP16 weights: chunk[(l*16+kt)*16+mt][lane][4 words(b32)] = 512B
__device__ __align__(1024) uint32_t g_Wh[3 * 32768];

// byte offset of logical act[k][p] inside the fp16 B-fragment smem buffer
__device__ __forceinline__ uint32_t faddr16(int k, int p) {
    return (((((uint32_t)(k >> 4) * NTILES + (p >> 3)) * 64
            + ((p & 7) * 4 + ((k >> 1) & 3)) * 2 + ((k >> 3) & 1)) << 2)
            + ((k & 1) << 1));
}

__global__ void convert_w_kernel(const float* __restrict__ W1,
                                 const float* __restrict__ W2,
                                 const float* __restrict__ W3) {
    int i = blockIdx.x * blockDim.x + threadIdx.x;   // 98304 threads, 1 b32 word each
    int reg = i & 3, lane = (i >> 2) & 31, mt = (i >> 7) & 15, kt = (i >> 11) & 15, l = i >> 15;
    int g = lane >> 2, t = lane & 3;
    int row = mt * 16 + g + (reg & 1) * 8;            // output channel o
    int col = kt * 16 + 2 * t + (reg >> 1) * 8;       // input channel c
    const float* W = (l == 0) ? W1 : ((l == 1) ? W2 : W3);
    __half lo = __float2half_rn(W[row * 256 + col]);
    __half hi = __float2half_rn(W[row * 256 + col + 1]);
    g_Wh[i] = (uint32_t)__half_as_ushort(lo) | ((uint32_t)__half_as_ushort(hi) << 16);
}

__device__ __forceinline__ void mma_f16(float* d, const uint32_t* a, const uint32_t* b) {
    asm volatile(
        "mma.sync.aligned.m16n8k16.row.col.f32.f16.f16.f32 "
        "{%0,%1,%2,%3}, {%4,%5,%6,%7}, {%8,%9}, {%0,%1,%2,%3};"
        : "+f"(d[0]), "+f"(d[1]), "+f"(d[2]), "+f"(d[3])
        : "r"(a[0]), "r"(a[1]), "r"(a[2]), "r"(a[3]), "r"(b[0]), "r"(b[1]));
}

#define CP16(d, s)  asm volatile("cp.async.ca.shared.global [%0], [%1], 16;" :: "r"(d), "l"(s) : "memory")
#define CPCOMMIT()  asm volatile("cp.async.commit_group;" ::: "memory")
#define CPWAIT1()   asm volatile("cp.async.wait_group 1;" ::: "memory")

// 256 threads = 8 warps (4 m x 2 n); warp tile 64 outputs x 24 positions.
// 3 CTAs / SM; per-warp double-buffered cp.async W staging.
__global__ __launch_bounds__(256, 3) void fused_kernel(
    const float* __restrict__ x,      // (32, 64, 64)
    const float* __restrict__ xc,     // (32, 128, 63, 64)
    const float* __restrict__ b1, const float* __restrict__ b2,
    const float* __restrict__ b3,
    float* __restrict__ out)          // (32, 256, 4032)
{
    extern __shared__ uint32_t actU[];
    char* const sc = (char*)actU;
    const int tid = threadIdx.x, lane = tid & 31, wid = tid >> 5;
    const int g = lane >> 2, t = lane & 3;
    const int wm = wid >> 1, wn = wid & 1;
    const int b = blockIdx.x / TPB, q0 = (blockIdx.x % TPB) * NPOS;

    // build 256ch x 48pos input tile directly as fp16 B-fragments
    for (int idx = tid; idx < 256 * NPOS; idx += 256) {
        int k = idx / NPOS, j = idx - k * NPOS;
        int q = q0 + j, h = q >> 6, w = q & 63;
        float v;
        if (k < 128)      v = xc[(size_t)(b * 128 + k) * 4032 + q];
        else if (k < 192) v = x[(b * 64 + (k - 128)) * 64 + w];
        else              v = x[(b * 64 + (k - 192)) * 64 + ((w - h - 1) & 63)];
        *(__half*)(sc + faddr16(k, j)) = __float2half_rn(v);
    }
    __syncthreads();

    // per-warp W staging region: two 2KB buffers
    char* const wstage = sc + SM_STAGE + wid * 4096;
    const uint32_t wstage_s =
        (uint32_t)__cvta_generic_to_shared(wstage) + (uint32_t)lane * 16u;

    const float* biases[3] = {b1, b2, b3};

    for (int l = 0; l < 3; l++) {
        float acc[4][3][4];
        #pragma unroll
        for (int mt = 0; mt < 4; mt++)
            #pragma unroll
            for (int nt = 0; nt < 3; nt++)
                #pragma unroll
                for (int r = 0; r < 4; r++) acc[mt][nt][r] = 0.f;

        const uint4* Wl = (const uint4*)g_Wh + (size_t)l * 8192;
        const uint2* Bb = (const uint2*)actU + lane;

        // prologue: stage k-step 0 into buffer 0
        {
            const uint4* s0 = Wl + (wm * 4) * 32 + lane;
            #pragma unroll
            for (int mt = 0; mt < 4; mt++) CP16(wstage_s + mt * 512, s0 + mt * 32);
            CPCOMMIT();
        }

        #pragma unroll 2
        for (int kt = 0; kt < 16; kt++) {
            if (kt < 15) {   // prefetch k-step kt+1 into the other buffer
                const uint4* s = Wl + ((kt + 1) * 16 + wm * 4) * 32 + lane;
                const uint32_t d = wstage_s + (uint32_t)(((kt + 1) & 1) * 2048);
                #pragma unroll
                for (int mt = 0; mt < 4; mt++) CP16(d + mt * 512, s + mt * 32);
            }
            CPCOMMIT();
            CPWAIT1();       // k-step kt's group is now complete

            uint32_t Br[3][2];
            #pragma unroll
            for (int nt = 0; nt < 3; nt++) {
                uint2 bv = Bb[(kt * NTILES + wn * 3 + nt) * 32];
                Br[nt][0] = bv.x; Br[nt][1] = bv.y;
            }
            const char* abuf = wstage + (kt & 1) * 2048 + lane * 16;
            #pragma unroll
            for (int mt = 0; mt < 4; mt++) {
                uint4 av = *(const uint4*)(abuf + mt * 512);
                uint32_t Ar[4] = {av.x, av.y, av.z, av.w};
                #pragma unroll
                for (int nt = 0; nt < 3; nt++)
                    mma_f16(acc[mt][nt], Ar, Br[nt]);
            }
        }

        __syncthreads();   // everyone done reading actU; safe to overwrite in place

        const float* bl = biases[l];
        if (l < 2) {
            #pragma unroll
            for (int mt = 0; mt < 4; mt++) {
                const int R0 = wm * 64 + mt * 16 + g;
                const float bb0 = bl[R0], bb8 = bl[R0 + 8];
                #pragma unroll
                for (int nt = 0; nt < 3; nt++) {
                    const int C0 = wn * 24 + nt * 8 + 2 * t;
                    *(__half*)(sc + faddr16(R0, C0)) =
                        __float2half_rn(fmaxf(acc[mt][nt][0] + bb0, 0.f));
                    *(__half*)(sc + faddr16(R0, C0 + 1)) =
                        __float2half_rn(fmaxf(acc[mt][nt][1] + bb0, 0.f));
                    *(__half*)(sc + faddr16(R0 + 8, C0)) =
                        __float2half_rn(fmaxf(acc[mt][nt][2] + bb8, 0.f));
                    *(__half*)(sc + faddr16(R0 + 8, C0 + 1)) =
                        __float2half_rn(fmaxf(acc[mt][nt][3] + bb8, 0.f));
                }
            }
            __syncthreads();
        } else {
            #pragma unroll
            for (int mt = 0; mt < 4; mt++) {
                const int R0 = wm * 64 + mt * 16 + g;
                const float bb0 = bl[R0], bb8 = bl[R0 + 8];
                float* p0 = out + ((size_t)(b * 256 + R0)) * 4032 + q0;
                float* p8 = p0 + (size_t)8 * 4032;
                #pragma unroll
                for (int nt = 0; nt < 3; nt++) {
                    const int C0 = wn * 24 + nt * 8 + 2 * t;
                    *(float2*)(p0 + C0) = make_float2(fmaxf(acc[mt][nt][0] + bb0, 0.f),
                                                      fmaxf(acc[mt][nt][1] + bb0, 0.f));
                    *(float2*)(p8 + C0) = make_float2(fmaxf(acc[mt][nt][2] + bb8, 0.f),
                                                      fmaxf(acc[mt][nt][3] + bb8, 0.f));
                }
            }
        }
    }
}

extern "C" void kernel_launch(void* const* d_in, const int* in_sizes, int n_in,
                              void* d_out, int out_size) {
    const float* x = nullptr; const float* xc = nullptr;
    const float* Ws[3] = {nullptr, nullptr, nullptr};
    const float* Bs[3] = {nullptr, nullptr, nullptr};
    int wi = 0, bi = 0;
    for (int i = 0; i < n_in; i++) {
        int sz = in_sizes[i];
        if (sz == 32 * 64 * 64)              x = (const float*)d_in[i];
        else if (sz == 32 * 128 * 63 * 64)   xc = (const float*)d_in[i];
        else if (sz == 256 * 256 && wi < 3)  Ws[wi++] = (const float*)d_in[i];
        else if (sz == 256 && bi < 3)        Bs[bi++] = (const float*)d_in[i];
    }
    convert_w_kernel<<<192, 512>>>(Ws[0], Ws[1], Ws[2]);
    cudaFuncSetAttribute(fused_kernel,
                         cudaFuncAttributeMaxDynamicSharedMemorySize, SMEM_TOTAL);
    fused_kernel<<<32 * TPB, 256, SMEM_TOTAL>>>(x, xc, Bs[0], Bs[1], Bs[2], (float*)d_out);
}

// round 13
// speedup vs baseline: 1.0285x; 1.0285x over previous
#include <cuda_runtime.h>
#include <cuda_fp16.h>
#include <cstdint>

#define NPOS 112            // positions per block; 4032 = 36*112
#define TPB  36
#define NTILES 14           // NPOS/8
#define SMEM_TOTAL (16 * NTILES * 64 * 4)   // 57344 B: fp16 B-fragment act buffer

// Fragment-major FP16 weights: chunk[(l*16+kt)*16+mt][lane][4 words(b32)] = 512B
__device__ __align__(1024) uint32_t g_Wh[3 * 32768];
// Precomputed fp32 tables: U[b][o][w] (x_rep part), V[b][o][j] (rolled part)
__device__ float g_U[32 * 256 * 64];
__device__ float g_V[32 * 256 * 64];

// byte offset of logical act[k][p] inside the fp16 B-fragment smem buffer
__device__ __forceinline__ uint32_t faddr16(int k, int p) {
    return (((((uint32_t)(k >> 4) * NTILES + (p >> 3)) * 64
            + ((p & 7) * 4 + ((k >> 1) & 3)) * 2 + ((k >> 3) & 1)) << 2)
            + ((k & 1) << 1));
}

__global__ void convert_w_kernel(const float* __restrict__ W1,
                                 const float* __restrict__ W2,
                                 const float* __restrict__ W3) {
    int i = blockIdx.x * blockDim.x + threadIdx.x;   // 98304 threads, 1 b32 word each
    int reg = i & 3, lane = (i >> 2) & 31, mt = (i >> 7) & 15, kt = (i >> 11) & 15, l = i >> 15;
    int g = lane >> 2, t = lane & 3;
    int row = mt * 16 + g + (reg & 1) * 8;            // output channel o
    int col = kt * 16 + 2 * t + (reg >> 1) * 8;       // input channel c
    const float* W = (l == 0) ? W1 : ((l == 1) ? W2 : W3);
    __half lo = __float2half_rn(W[row * 256 + col]);
    __half hi = __float2half_rn(W[row * 256 + col + 1]);
    g_Wh[i] = (uint32_t)__half_as_ushort(lo) | ((uint32_t)__half_as_ushort(hi) << 16);
}

// U[b][o][w] = sum_c W1[o][128+c] x[b][c][w];  V[b][o][w] = sum_c W1[o][192+c] x[b][c][w]
__global__ void uv_kernel(const float* __restrict__ x, const float* __restrict__ W1) {
    int i = blockIdx.x * blockDim.x + threadIdx.x;   // 524288 threads
    int w = i & 63, o = (i >> 6) & 255, b = i >> 14;
    const float* xb = x + (size_t)b * 4096 + w;
    const float* w1 = W1 + (size_t)o * 256;
    float u = 0.f, v = 0.f;
    #pragma unroll 8
    for (int c = 0; c < 64; c++) {
        float xv = xb[c * 64];
        u = fmaf(w1[128 + c], xv, u);
        v = fmaf(w1[192 + c], xv, v);
    }
    g_U[i] = u; g_V[i] = v;
}

__device__ __forceinline__ void mma_f16(float* d, const uint32_t* a, const uint32_t* b) {
    asm volatile(
        "mma.sync.aligned.m16n8k16.row.col.f32.f16.f16.f32 "
        "{%0,%1,%2,%3}, {%4,%5,%6,%7}, {%8,%9}, {%0,%1,%2,%3};"
        : "+f"(d[0]), "+f"(d[1]), "+f"(d[2]), "+f"(d[3])
        : "r"(a[0]), "r"(a[1]), "r"(a[2]), "r"(a[3]), "r"(b[0]), "r"(b[1]));
}

// 512 threads = 16 warps (8 m x 2 n); warp tile 32 outputs x 56 positions.
// Layer 1 runs K=128 (xc only); x_rep/rolled contributions come from U/V tables.
__global__ __launch_bounds__(512, 1) void fused_kernel(
    const float* __restrict__ x,      // (32, 64, 64)
    const float* __restrict__ xc,     // (32, 128, 63, 64)
    const float* __restrict__ b1, const float* __restrict__ b2,
    const float* __restrict__ b3,
    float* __restrict__ out)          // (32, 256, 4032)
{
    extern __shared__ uint32_t actU[];
    char* const sc = (char*)actU;
    const int tid = threadIdx.x, lane = tid & 31, wid = tid >> 5;
    const int g = lane >> 2, t = lane & 3;
    const int wm = wid >> 1, wn = wid & 1;
    const int b = blockIdx.x / TPB, q0 = (blockIdx.x % TPB) * NPOS;

    // build 128ch x 112pos xc tile directly as fp16 B-fragments (layer-1 K=128)
    for (int idx = tid; idx < 128 * NPOS; idx += 512) {
        int k = idx / NPOS, j = idx - k * NPOS;
        *(__half*)(sc + faddr16(k, j)) =
            __float2half_rn(xc[(size_t)(b * 128 + k) * 4032 + q0 + j]);
    }
    __syncthreads();

    const float* biases[3] = {b1, b2, b3};

    for (int l = 0; l < 3; l++) {
        float acc[2][7][4];
        #pragma unroll
        for (int mt = 0; mt < 2; mt++)
            #pragma unroll
            for (int nt = 0; nt < 7; nt++)
                #pragma unroll
                for (int r = 0; r < 4; r++) acc[mt][nt][r] = 0.f;

        const uint4* Ab = (const uint4*)g_Wh + (size_t)l * 8192 + lane;
        const uint2* Bb = (const uint2*)actU + lane;
        const int ktn = (l == 0) ? 8 : 16;   // layer 1: K=128 only

        #pragma unroll 2
        for (int kt = 0; kt < ktn; kt++) {
            uint32_t Br[7][2];
            #pragma unroll
            for (int nt = 0; nt < 7; nt++) {
                uint2 bv = Bb[(kt * NTILES + wn * 7 + nt) * 32];
                Br[nt][0] = bv.x; Br[nt][1] = bv.y;
            }
            uint32_t Ar[2][4];
            #pragma unroll
            for (int mt = 0; mt < 2; mt++) {
                uint4 av = Ab[(kt * 16 + wm * 2 + mt) * 32];
                Ar[mt][0] = av.x; Ar[mt][1] = av.y; Ar[mt][2] = av.z; Ar[mt][3] = av.w;
            }
            #pragma unroll
            for (int mt = 0; mt < 2; mt++)
                #pragma unroll
                for (int nt = 0; nt < 7; nt++)
                    mma_f16(acc[mt][nt], Ar[mt], Br[nt]);
        }

        __syncthreads();   // everyone done reading actU; safe to overwrite in place

        const float* bl = biases[l];
        if (l == 0) {
            const float* Ub = g_U + (size_t)b * 16384;
            const float* Vb = g_V + (size_t)b * 16384;
            #pragma unroll
            for (int mt = 0; mt < 2; mt++) {
                const int R0 = wm * 32 + mt * 16 + g;
                const float bb0 = bl[R0], bb8 = bl[R0 + 8];
                const float* U0 = Ub + R0 * 64;
                const float* V0 = Vb + R0 * 64;
                const float* U8 = U0 + 512;   // (R0+8)*64
                const float* V8 = V0 + 512;
                #pragma unroll
                for (int nt = 0; nt < 7; nt++) {
                    const int C0 = wn * 56 + nt * 8 + 2 * t;
                    const int qa = q0 + C0, qb = qa + 1;
                    const int wa = qa & 63, ja = (wa - (qa >> 6) - 1) & 63;
                    const int wb = qb & 63, jb = (wb - (qb >> 6) - 1) & 63;
                    *(__half*)(sc + faddr16(R0, C0)) = __float2half_rn(
                        fmaxf(acc[mt][nt][0] + U0[wa] + V0[ja] + bb0, 0.f));
                    *(__half*)(sc + faddr16(R0, C0 + 1)) = __float2half_rn(
                        fmaxf(acc[mt][nt][1] + U0[wb] + V0[jb] + bb0, 0.f));
                    *(__half*)(sc + faddr16(R0 + 8, C0)) = __float2half_rn(
                        fmaxf(acc[mt][nt][2] + U8[wa] + V8[ja] + bb8, 0.f));
                    *(__half*)(sc + faddr16(R0 + 8, C0 + 1)) = __float2half_rn(
                        fmaxf(acc[mt][nt][3] + U8[wb] + V8[jb] + bb8, 0.f));
                }
            }
            __syncthreads();
        } else if (l == 1) {
            #pragma unroll
            for (int mt = 0; mt < 2; mt++) {
                const int R0 = wm * 32 + mt * 16 + g;
                const float bb0 = bl[R0], bb8 = bl[R0 + 8];
                #pragma unroll
                for (int nt = 0; nt < 7; nt++) {
                    const int C0 = wn * 56 + nt * 8 + 2 * t;
                    *(__half*)(sc + faddr16(R0, C0)) =
                        __float2half_rn(fmaxf(acc[mt][nt][0] + bb0, 0.f));
                    *(__half*)(sc + faddr16(R0, C0 + 1)) =
                        __float2half_rn(fmaxf(acc[mt][nt][1] + bb0, 0.f));
                    *(__half*)(sc + faddr16(R0 + 8, C0)) =
                        __float2half_rn(fmaxf(acc[mt][nt][2] + bb8, 0.f));
                    *(__half*)(sc + faddr16(R0 + 8, C0 + 1)) =
                        __float2half_rn(fmaxf(acc[mt][nt][3] + bb8, 0.f));
                }
            }
            __syncthreads();
        } else {
            #pragma unroll
            for (int mt = 0; mt < 2; mt++) {
                const int R0 = wm * 32 + mt * 16 + g;
                const float bb0 = bl[R0], bb8 = bl[R0 + 8];
                float* p0 = out + ((size_t)(b * 256 + R0)) * 4032 + q0;
                float* p8 = p0 + (size_t)8 * 4032;
                #pragma unroll
                for (int nt = 0; nt < 7; nt++) {
                    const int C0 = wn * 56 + nt * 8 + 2 * t;
                    *(float2*)(p0 + C0) = make_float2(fmaxf(acc[mt][nt][0] + bb0, 0.f),
                                                      fmaxf(acc[mt][nt][1] + bb0, 0.f));
                    *(float2*)(p8 + C0) = make_float2(fmaxf(acc[mt][nt][2] + bb8, 0.f),
                                                      fmaxf(acc[mt][nt][3] + bb8, 0.f));
                }
            }
        }
    }
}

extern "C" void kernel_launch(void* const* d_in, const int* in_sizes, int n_in,
                              void* d_out, int out_size) {
    const float* x = nullptr; const float* xc = nullptr;
    const float* Ws[3] = {nullptr, nullptr, nullptr};
    const float* Bs[3] = {nullptr, nullptr, nullptr};
    int wi = 0, bi = 0;
    for (int i = 0; i < n_in; i++) {
        int sz = in_sizes[i];
        if (sz == 32 * 64 * 64)              x = (const float*)d_in[i];
        else if (sz == 32 * 128 * 63 * 64)   xc = (const float*)d_in[i];
        else if (sz == 256 * 256 && wi < 3)  Ws[wi++] = (const float*)d_in[i];
        else if (sz == 256 && bi < 3)        Bs[bi++] = (const float*)d_in[i];
    }
    convert_w_kernel<<<192, 512>>>(Ws[0], Ws[1], Ws[2]);
    uv_kernel<<<1024, 512>>>(x, Ws[0]);
    cudaFuncSetAttribute(fused_kernel,
                         cudaFuncAttributeMaxDynamicSharedMemorySize, SMEM_TOTAL);
    fused_kernel<<<32 * TPB, 512, SMEM_TOTAL>>>(x, xc, Bs[0], Bs[1], Bs[2], (float*)d_out);
}

// round 14
// speedup vs baseline: 1.1885x; 1.1556x over previous
#include <cuda_runtime.h>
#include <cuda_fp16.h>
#include <cstdint>

#define NPOS 112            // positions per block; 4032 = 36*112
#define TPB  36
#define NTILES 14           // NPOS/8
#define SM_UV   57344       // act buffer is [0, 57344)
#define UVSTRIDE 65         // floats per U/V row (bank-conflict spread)
#define SMEM_TOTAL (57344 + 2 * 256 * UVSTRIDE * 4)   // 190464 B

// Fragment-major FP16 weights: chunk[(l*16+kt)*16+mt][lane][4 words(b32)] = 512B
__device__ __align__(1024) uint32_t g_Wh[3 * 32768];
// Precomputed fp32 tables: U[b][o][w] (x_rep part), V[b][o][j] (rolled part)
__device__ float g_U[32 * 256 * 64];
__device__ float g_V[32 * 256 * 64];

// byte offset of logical act[k][p] inside the fp16 B-fragment smem buffer
__device__ __forceinline__ uint32_t faddr16(int k, int p) {
    return (((((uint32_t)(k >> 4) * NTILES + (p >> 3)) * 64
            + ((p & 7) * 4 + ((k >> 1) & 3)) * 2 + ((k >> 3) & 1)) << 2)
            + ((k & 1) << 1));
}

__global__ void convert_w_kernel(const float* __restrict__ W1,
                                 const float* __restrict__ W2,
                                 const float* __restrict__ W3) {
    int i = blockIdx.x * blockDim.x + threadIdx.x;   // 98304 threads, 1 b32 word each
    int reg = i & 3, lane = (i >> 2) & 31, mt = (i >> 7) & 15, kt = (i >> 11) & 15, l = i >> 15;
    int g = lane >> 2, t = lane & 3;
    int row = mt * 16 + g + (reg & 1) * 8;            // output channel o
    int col = kt * 16 + 2 * t + (reg >> 1) * 8;       // input channel c
    const float* W = (l == 0) ? W1 : ((l == 1) ? W2 : W3);
    __half lo = __float2half_rn(W[row * 256 + col]);
    __half hi = __float2half_rn(W[row * 256 + col + 1]);
    g_Wh[i] = (uint32_t)__half_as_ushort(lo) | ((uint32_t)__half_as_ushort(hi) << 16);
}

// U[b][o][w] = sum_c W1[o][128+c] x[b][c][w];  V[b][o][w] = sum_c W1[o][192+c] x[b][c][w]
__global__ void uv_kernel(const float* __restrict__ x, const float* __restrict__ W1) {
    int i = blockIdx.x * blockDim.x + threadIdx.x;   // 524288 threads
    int w = i & 63, o = (i >> 6) & 255, b = i >> 14;
    const float* xb = x + (size_t)b * 4096 + w;
    const float* w1 = W1 + (size_t)o * 256;
    float u = 0.f, v = 0.f;
    #pragma unroll 8
    for (int c = 0; c < 64; c++) {
        float xv = xb[c * 64];
        u = fmaf(w1[128 + c], xv, u);
        v = fmaf(w1[192 + c], xv, v);
    }
    g_U[i] = u; g_V[i] = v;
}

__device__ __forceinline__ void mma_f16(float* d, const uint32_t* a, const uint32_t* b) {
    asm volatile(
        "mma.sync.aligned.m16n8k16.row.col.f32.f16.f16.f32 "
        "{%0,%1,%2,%3}, {%4,%5,%6,%7}, {%8,%9}, {%0,%1,%2,%3};"
        : "+f"(d[0]), "+f"(d[1]), "+f"(d[2]), "+f"(d[3])
        : "r"(a[0]), "r"(a[1]), "r"(a[2]), "r"(a[3]), "r"(b[0]), "r"(b[1]));
}

// 512 threads = 16 warps (8 m x 2 n); warp tile 32 outputs x 56 positions.
// Layer 1 runs K=128 (xc only); x_rep/rolled contributions come from smem-staged U/V.
__global__ __launch_bounds__(512, 1) void fused_kernel(
    const float* __restrict__ x,      // (32, 64, 64)
    const float* __restrict__ xc,     // (32, 128, 63, 64)
    const float* __restrict__ b1, const float* __restrict__ b2,
    const float* __restrict__ b3,
    float* __restrict__ out)          // (32, 256, 4032)
{
    extern __shared__ uint32_t actU[];
    char* const sc = (char*)actU;
    float* const Us = (float*)(sc + SM_UV);
    float* const Vs = Us + 256 * UVSTRIDE;
    const int tid = threadIdx.x, lane = tid & 31, wid = tid >> 5;
    const int g = lane >> 2, t = lane & 3;
    const int wm = wid >> 1, wn = wid & 1;
    const int b = blockIdx.x / TPB, q0 = (blockIdx.x % TPB) * NPOS;

    // build 128ch x 112pos xc tile directly as fp16 B-fragments (layer-1 K=128)
    for (int idx = tid; idx < 128 * NPOS; idx += 512) {
        int k = idx / NPOS, j = idx - k * NPOS;
        *(__half*)(sc + faddr16(k, j)) =
            __float2half_rn(xc[(size_t)(b * 128 + k) * 4032 + q0 + j]);
    }
    // stage this batch's U/V tables into smem (coalesced; L2-hot)
    {
        const float* Ug = g_U + (size_t)b * 16384;
        const float* Vg = g_V + (size_t)b * 16384;
        for (int idx = tid; idx < 16384; idx += 512) {
            int o = idx >> 6, w = idx & 63;
            Us[o * UVSTRIDE + w] = Ug[idx];
            Vs[o * UVSTRIDE + w] = Vg[idx];
        }
    }
    __syncthreads();

    const float* biases[3] = {b1, b2, b3};

    for (int l = 0; l < 3; l++) {
        float acc[2][7][4];
        #pragma unroll
        for (int mt = 0; mt < 2; mt++)
            #pragma unroll
            for (int nt = 0; nt < 7; nt++)
                #pragma unroll
                for (int r = 0; r < 4; r++) acc[mt][nt][r] = 0.f;

        const uint4* Ab = (const uint4*)g_Wh + (size_t)l * 8192 + lane;
        const uint2* Bb = (const uint2*)actU + lane;
        const int ktn = (l == 0) ? 8 : 16;   // layer 1: K=128 only

        #pragma unroll 2
        for (int kt = 0; kt < ktn; kt++) {
            uint32_t Br[7][2];
            #pragma unroll
            for (int nt = 0; nt < 7; nt++) {
                uint2 bv = Bb[(kt * NTILES + wn * 7 + nt) * 32];
                Br[nt][0] = bv.x; Br[nt][1] = bv.y;
            }
            uint32_t Ar[2][4];
            #pragma unroll
            for (int mt = 0; mt < 2; mt++) {
                uint4 av = Ab[(kt * 16 + wm * 2 + mt) * 32];
                Ar[mt][0] = av.x; Ar[mt][1] = av.y; Ar[mt][2] = av.z; Ar[mt][3] = av.w;
            }
            #pragma unroll
            for (int mt = 0; mt < 2; mt++)
                #pragma unroll
                for (int nt = 0; nt < 7; nt++)
                    mma_f16(acc[mt][nt], Ar[mt], Br[nt]);
        }

        __syncthreads();   // everyone done reading actU; safe to overwrite in place

        const float* bl = biases[l];
        if (l == 0) {
            #pragma unroll
            for (int mt = 0; mt < 2; mt++) {
                const int R0 = wm * 32 + mt * 16 + g;
                const float bb0 = bl[R0], bb8 = bl[R0 + 8];
                const float* U0 = Us + R0 * UVSTRIDE;
                const float* V0 = Vs + R0 * UVSTRIDE;
                const float* U8 = U0 + 8 * UVSTRIDE;
                const float* V8 = V0 + 8 * UVSTRIDE;
                #pragma unroll
                for (int nt = 0; nt < 7; nt++) {
                    const int C0 = wn * 56 + nt * 8 + 2 * t;
                    const int qa = q0 + C0, qb = qa + 1;
                    const int wa = qa & 63, ja = (wa - (qa >> 6) - 1) & 63;
                    const int wb = qb & 63, jb = (wb - (qb >> 6) - 1) & 63;
                    *(__half*)(sc + faddr16(R0, C0)) = __float2half_rn(
                        fmaxf(acc[mt][nt][0] + U0[wa] + V0[ja] + bb0, 0.f));
                    *(__half*)(sc + faddr16(R0, C0 + 1)) = __float2half_rn(
                        fmaxf(acc[mt][nt][1] + U0[wb] + V0[jb] + bb0, 0.f));
                    *(__half*)(sc + faddr16(R0 + 8, C0)) = __float2half_rn(
                        fmaxf(acc[mt][nt][2] + U8[wa] + V8[ja] + bb8, 0.f));
                    *(__half*)(sc + faddr16(R0 + 8, C0 + 1)) = __float2half_rn(
                        fmaxf(acc[mt][nt][3] + U8[wb] + V8[jb] + bb8, 0.f));
                }
            }
            __syncthreads();
        } else if (l == 1) {
            #pragma unroll
            for (int mt = 0; mt < 2; mt++) {
                const int R0 = wm * 32 + mt * 16 + g;
                const float bb0 = bl[R0], bb8 = bl[R0 + 8];
                #pragma unroll
                for (int nt = 0; nt < 7; nt++) {
                    const int C0 = wn * 56 + nt * 8 + 2 * t;
                    *(__half*)(sc + faddr16(R0, C0)) =
                        __float2half_rn(fmaxf(acc[mt][nt][0] + bb0, 0.f));
                    *(__half*)(sc + faddr16(R0, C0 + 1)) =
                        __float2half_rn(fmaxf(acc[mt][nt][1] + bb0, 0.f));
                    *(__half*)(sc + faddr16(R0 + 8, C0)) =
                        __float2half_rn(fmaxf(acc[mt][nt][2] + bb8, 0.f));
                    *(__half*)(sc + faddr16(R0 + 8, C0 + 1)) =
                        __float2half_rn(fmaxf(acc[mt][nt][3] + bb8, 0.f));
                }
            }
            __syncthreads();
        } else {
            #pragma unroll
            for (int mt = 0; mt < 2; mt++) {
                const int R0 = wm * 32 + mt * 16 + g;
                const float bb0 = bl[R0], bb8 = bl[R0 + 8];
                float* p0 = out + ((size_t)(b * 256 + R0)) * 4032 + q0;
                float* p8 = p0 + (size_t)8 * 4032;
                #pragma unroll
                for (int nt = 0; nt < 7; nt++) {
                    const int C0 = wn * 56 + nt * 8 + 2 * t;
                    *(float2*)(p0 + C0) = make_float2(fmaxf(acc[mt][nt][0] + bb0, 0.f),
                                                      fmaxf(acc[mt][nt][1] + bb0, 0.f));
                    *(float2*)(p8 + C0) = make_float2(fmaxf(acc[mt][nt][2] + bb8, 0.f),
                                                      fmaxf(acc[mt][nt][3] + bb8, 0.f));
                }
            }
        }
    }
}

extern "C" void kernel_launch(void* const* d_in, const int* in_sizes, int n_in,
                              void* d_out, int out_size) {
    const float* x = nullptr; const float* xc = nullptr;
    const float* Ws[3] = {nullptr, nullptr, nullptr};
    const float* Bs[3] = {nullptr, nullptr, nullptr};
    int wi = 0, bi = 0;
    for (int i = 0; i < n_in; i++) {
        int sz = in_sizes[i];
        if (sz == 32 * 64 * 64)              x = (const float*)d_in[i];
        else if (sz == 32 * 128 * 63 * 64)   xc = (const float*)d_in[i];
        else if (sz == 256 * 256 && wi < 3)  Ws[wi++] = (const float*)d_in[i];
        else if (sz == 256 && bi < 3)        Bs[bi++] = (const float*)d_in[i];
    }
    convert_w_kernel<<<192, 512>>>(Ws[0], Ws[1], Ws[2]);
    uv_kernel<<<1024, 512>>>(x, Ws[0]);
    cudaFuncSetAttribute(fused_kernel,
                         cudaFuncAttributeMaxDynamicSharedMemorySize, SMEM_TOTAL);
    fused_kernel<<<32 * TPB, 512, SMEM_TOTAL>>>(x, xc, Bs[0], Bs[1], Bs[2], (float*)d_out);
}

// round 15
// speedup vs baseline: 1.2150x; 1.0223x over previous
#include <cuda_runtime.h>
#include <cuda_fp16.h>
#include <cstdint>

#define NPOS 112            // positions per block; 4032 = 36*112
#define TPB  36
#define NTILES 14           // NPOS/8
#define SM_UV   57344       // act buffer is [0, 57344)
#define UVSTRIDE 65         // floats per U/V row (bank-conflict spread)
#define SMEM_TOTAL (57344 + 2 * 256 * UVSTRIDE * 4)   // 190464 B

// Fragment-major FP16 weights: chunk[(l*16+kt)*16+mt][lane][4 words(b32)] = 512B
__device__ __align__(1024) uint32_t g_Wh[3 * 32768];
// Precomputed fp32 tables: U[b][o][w] (x_rep part), V[b][o][j] (rolled part)
__device__ float g_U[32 * 256 * 64];
__device__ float g_V[32 * 256 * 64];

// byte offset of logical act[k][p] inside the fp16 B-fragment smem buffer
__device__ __forceinline__ uint32_t faddr16(int k, int p) {
    return (((((uint32_t)(k >> 4) * NTILES + (p >> 3)) * 64
            + ((p & 7) * 4 + ((k >> 1) & 3)) * 2 + ((k >> 3) & 1)) << 2)
            + ((k & 1) << 1));
}

// Merged prologue: blocks [0,192) convert W to fragment-major fp16;
// blocks [192,1216) compute the U/V tables. One launch, fully parallel.
__global__ __launch_bounds__(512) void prologue_kernel(
    const float* __restrict__ x,
    const float* __restrict__ W1, const float* __restrict__ W2,
    const float* __restrict__ W3)
{
    if (blockIdx.x < 192) {
        int i = blockIdx.x * 512 + threadIdx.x;   // 98304 threads, 1 b32 word each
        int reg = i & 3, lane = (i >> 2) & 31, mt = (i >> 7) & 15, kt = (i >> 11) & 15, l = i >> 15;
        int g = lane >> 2, t = lane & 3;
        int row = mt * 16 + g + (reg & 1) * 8;            // output channel o
        int col = kt * 16 + 2 * t + (reg >> 1) * 8;       // input channel c
        const float* W = (l == 0) ? W1 : ((l == 1) ? W2 : W3);
        __half lo = __float2half_rn(W[row * 256 + col]);
        __half hi = __float2half_rn(W[row * 256 + col + 1]);
        g_Wh[i] = (uint32_t)__half_as_ushort(lo) | ((uint32_t)__half_as_ushort(hi) << 16);
    } else {
        int i = (blockIdx.x - 192) * 512 + threadIdx.x;   // 524288 threads
        int w = i & 63, o = (i >> 6) & 255, b = i >> 14;
        const float* xb = x + (size_t)b * 4096 + w;
        const float* w1 = W1 + (size_t)o * 256;
        float u = 0.f, v = 0.f;
        #pragma unroll 8
        for (int c = 0; c < 64; c++) {
            float xv = xb[c * 64];
            u = fmaf(w1[128 + c], xv, u);
            v = fmaf(w1[192 + c], xv, v);
        }
        g_U[i] = u; g_V[i] = v;
    }
}

__device__ __forceinline__ void mma_f16(float* d, const uint32_t* a, const uint32_t* b) {
    asm volatile(
        "mma.sync.aligned.m16n8k16.row.col.f32.f16.f16.f32 "
        "{%0,%1,%2,%3}, {%4,%5,%6,%7}, {%8,%9}, {%0,%1,%2,%3};"
        : "+f"(d[0]), "+f"(d[1]), "+f"(d[2]), "+f"(d[3])
        : "r"(a[0]), "r"(a[1]), "r"(a[2]), "r"(a[3]), "r"(b[0]), "r"(b[1]));
}

// 512 threads = 16 warps (8 m x 2 n); warp tile 32 outputs x 56 positions.
// Layer 1 runs K=128 (xc only); x_rep/rolled contributions come from smem-staged U/V.
__global__ __launch_bounds__(512, 1) void fused_kernel(
    const float* __restrict__ x,      // (32, 64, 64)
    const float* __restrict__ xc,     // (32, 128, 63, 64)
    const float* __restrict__ b1, const float* __restrict__ b2,
    const float* __restrict__ b3,
    float* __restrict__ out)          // (32, 256, 4032)
{
    extern __shared__ uint32_t actU[];
    char* const sc = (char*)actU;
    float* const Us = (float*)(sc + SM_UV);
    float* const Vs = Us + 256 * UVSTRIDE;
    const int tid = threadIdx.x, lane = tid & 31, wid = tid >> 5;
    const int g = lane >> 2, t = lane & 3;
    const int wm = wid >> 1, wn = wid & 1;
    const int b = blockIdx.x / TPB, q0 = (blockIdx.x % TPB) * NPOS;

    // stage this batch's U/V tables into smem first (L2-hot, short latency)...
    {
        const float* Ug = g_U + (size_t)b * 16384;
        const float* Vg = g_V + (size_t)b * 16384;
        for (int idx = tid; idx < 16384; idx += 512) {
            int o = idx >> 6, w = idx & 63;
            Us[o * UVSTRIDE + w] = Ug[idx];
            Vs[o * UVSTRIDE + w] = Vg[idx];
        }
    }
    // ...then build 128ch x 112pos xc tile as fp16 B-fragments (DRAM latency overlaps above)
    for (int idx = tid; idx < 128 * NPOS; idx += 512) {
        int k = idx / NPOS, j = idx - k * NPOS;
        *(__half*)(sc + faddr16(k, j)) =
            __float2half_rn(xc[(size_t)(b * 128 + k) * 4032 + q0 + j]);
    }
    __syncthreads();

    const float* biases[3] = {b1, b2, b3};

    for (int l = 0; l < 3; l++) {
        float acc[2][7][4];
        #pragma unroll
        for (int mt = 0; mt < 2; mt++)
            #pragma unroll
            for (int nt = 0; nt < 7; nt++)
                #pragma unroll
                for (int r = 0; r < 4; r++) acc[mt][nt][r] = 0.f;

        const uint4* Ab = (const uint4*)g_Wh + (size_t)l * 8192 + lane;
        const uint2* Bb = (const uint2*)actU + lane;
        const int ktn = (l == 0) ? 8 : 16;   // layer 1: K=128 only

        #pragma unroll 4
        for (int kt = 0; kt < ktn; kt++) {
            uint32_t Br[7][2];
            #pragma unroll
            for (int nt = 0; nt < 7; nt++) {
                uint2 bv = Bb[(kt * NTILES + wn * 7 + nt) * 32];
                Br[nt][0] = bv.x; Br[nt][1] = bv.y;
            }
            uint32_t Ar[2][4];
            #pragma unroll
            for (int mt = 0; mt < 2; mt++) {
                uint4 av = Ab[(kt * 16 + wm * 2 + mt) * 32];
                Ar[mt][0] = av.x; Ar[mt][1] = av.y; Ar[mt][2] = av.z; Ar[mt][3] = av.w;
            }
            #pragma unroll
            for (int mt = 0; mt < 2; mt++)
                #pragma unroll
                for (int nt = 0; nt < 7; nt++)
                    mma_f16(acc[mt][nt], Ar[mt], Br[nt]);
        }

        __syncthreads();   // everyone done reading actU; safe to overwrite in place

        const float* bl = biases[l];
        if (l == 0) {
            #pragma unroll
            for (int mt = 0; mt < 2; mt++) {
                const int R0 = wm * 32 + mt * 16 + g;
                const float bb0 = bl[R0], bb8 = bl[R0 + 8];
                const float* U0 = Us + R0 * UVSTRIDE;
                const float* V0 = Vs + R0 * UVSTRIDE;
                const float* U8 = U0 + 8 * UVSTRIDE;
                const float* V8 = V0 + 8 * UVSTRIDE;
                #pragma unroll
                for (int nt = 0; nt < 7; nt++) {
                    const int C0 = wn * 56 + nt * 8 + 2 * t;
                    const int qa = q0 + C0, qb = qa + 1;
                    const int wa = qa & 63, ja = (wa - (qa >> 6) - 1) & 63;
                    const int wb = qb & 63, jb = (wb - (qb >> 6) - 1) & 63;
                    *(__half*)(sc + faddr16(R0, C0)) = __float2half_rn(
                        fmaxf(acc[mt][nt][0] + U0[wa] + V0[ja] + bb0, 0.f));
                    *(__half*)(sc + faddr16(R0, C0 + 1)) = __float2half_rn(
                        fmaxf(acc[mt][nt][1] + U0[wb] + V0[jb] + bb0, 0.f));
                    *(__half*)(sc + faddr16(R0 + 8, C0)) = __float2half_rn(
                        fmaxf(acc[mt][nt][2] + U8[wa] + V8[ja] + bb8, 0.f));
                    *(__half*)(sc + faddr16(R0 + 8, C0 + 1)) = __float2half_rn(
                        fmaxf(acc[mt][nt][3] + U8[wb] + V8[jb] + bb8, 0.f));
                }
            }
            __syncthreads();
        } else if (l == 1) {
            #pragma unroll
            for (int mt = 0; mt < 2; mt++) {
                const int R0 = wm * 32 + mt * 16 + g;
                const float bb0 = bl[R0], bb8 = bl[R0 + 8];
                #pragma unroll
                for (int nt = 0; nt < 7; nt++) {
                    const int C0 = wn * 56 + nt * 8 + 2 * t;
                    *(__half*)(sc + faddr16(R0, C0)) =
                        __float2half_rn(fmaxf(acc[mt][nt][0] + bb0, 0.f));
                    *(__half*)(sc + faddr16(R0, C0 + 1)) =
                        __float2half_rn(fmaxf(acc[mt][nt][1] + bb0, 0.f));
                    *(__half*)(sc + faddr16(R0 + 8, C0)) =
                        __float2half_rn(fmaxf(acc[mt][nt][2] + bb8, 0.f));
                    *(__half*)(sc + faddr16(R0 + 8, C0 + 1)) =
                        __float2half_rn(fmaxf(acc[mt][nt][3] + bb8, 0.f));
                }
            }
            __syncthreads();
        } else {
            #pragma unroll
            for (int mt = 0; mt < 2; mt++) {
                const int R0 = wm * 32 + mt * 16 + g;
                const float bb0 = bl[R0], bb8 = bl[R0 + 8];
                float* p0 = out + ((size_t)(b * 256 + R0)) * 4032 + q0;
                float* p8 = p0 + (size_t)8 * 4032;
                #pragma unroll
                for (int nt = 0; nt < 7; nt++) {
                    const int C0 = wn * 56 + nt * 8 + 2 * t;
                    *(float2*)(p0 + C0) = make_float2(fmaxf(acc[mt][nt][0] + bb0, 0.f),
                                                      fmaxf(acc[mt][nt][1] + bb0, 0.f));
                    *(float2*)(p8 + C0) = make_float2(fmaxf(acc[mt][nt][2] + bb8, 0.f),
                                                      fmaxf(acc[mt][nt][3] + bb8, 0.f));
                }
            }
        }
    }
}

extern "C" void kernel_launch(void* const* d_in, const int* in_sizes, int n_in,
                              void* d_out, int out_size) {
    const float* x = nullptr; const float* xc = nullptr;
    const float* Ws[3] = {nullptr, nullptr, nullptr};
    const float* Bs[3] = {nullptr, nullptr, nullptr};
    int wi = 0, bi = 0;
    for (int i = 0; i < n_in; i++) {
        int sz = in_sizes[i];
        if (sz == 32 * 64 * 64)              x = (const float*)d_in[i];
        else if (sz == 32 * 128 * 63 * 64)   xc = (const float*)d_in[i];
        else if (sz == 256 * 256 && wi < 3)  Ws[wi++] = (const float*)d_in[i];
        else if (sz == 256 && bi < 3)        Bs[bi++] = (const float*)d_in[i];
    }
    prologue_kernel<<<1216, 512>>>(x, Ws[0], Ws[1], Ws[2]);
    cudaFuncSetAttribute(fused_kernel,
                         cudaFuncAttributeMaxDynamicSharedMemorySize, SMEM_TOTAL);
    fused_kernel<<<32 * TPB, 512, SMEM_TOTAL>>>(x, xc, Bs[0], Bs[1], Bs[2], (float*)d_out);
}